// round 2
// baseline (speedup 1.0000x reference)
#include <cuda_runtime.h>
#include <cuda_bf16.h>
#include <cfloat>
#include <climits>

// ---------------------------------------------------------------------------
// Problem shape (fixed for this problem id)
//   query        [B=256,  C=1024] f32
//   bank         [M=200000, C=1024] f32
//   trajectories [M, T=8, D=3] f32  (TD = 24 floats per row)
//   k = 16
// Output: trajectories[nn_idx]  -> [B, 16, 8, 3] = B*16*24 floats,
// neighbors sorted by ascending L2 distance (ties: lower index first),
// matching jax.lax.top_k(-dist, k).
// ---------------------------------------------------------------------------

#define C_DIM   1024
#define B_MAX   256
#define M_MAX   200000
#define KSEL    16
#define TD_MAX  24

// Scratch (allocation-free rule: __device__ globals)
__device__ float g_score[(size_t)B_MAX * M_MAX];   // ~205 MB
__device__ float g_bsq[M_MAX];

// ---------------------------------------------------------------------------
// Kernel 1: bank row squared norms. One warp per row.
// ---------------------------------------------------------------------------
__global__ void bank_sq_kernel(const float* __restrict__ bank, int M) {
    int warp = (blockIdx.x * blockDim.x + threadIdx.x) >> 5;
    int lane = threadIdx.x & 31;
    if (warp >= M) return;
    const float4* row = reinterpret_cast<const float4*>(bank + (size_t)warp * C_DIM);
    float acc = 0.f;
#pragma unroll 8
    for (int j = lane; j < C_DIM / 4; j += 32) {
        float4 v = row[j];
        acc += v.x * v.x + v.y * v.y + v.z * v.z + v.w * v.w;
    }
#pragma unroll
    for (int off = 16; off > 0; off >>= 1)
        acc += __shfl_xor_sync(0xffffffffu, acc, off);
    if (lane == 0) g_bsq[warp] = acc;
}

// ---------------------------------------------------------------------------
// Kernel 2: score[b, m] = ||p_m||^2 - 2 * (q_b . p_m)
// Classic 128x128x16 SGEMM tiling, packed f32x2 FMA inner loop.
// ---------------------------------------------------------------------------
#define BM 128
#define BN 128
#define BK 16

__global__ __launch_bounds__(256)
void gemm_score_kernel(const float* __restrict__ Q,
                       const float* __restrict__ Bank,
                       int M) {
    __shared__ float As[BK][BM];
    __shared__ float Bs[BK][BN];

    const int tid = threadIdx.x;
    const int bm  = blockIdx.y * BM;   // query tile base (always in-range)
    const int bn  = blockIdx.x * BN;   // bank tile base (may have tail)
    const int tx  = tid & 15;          // N direction (0..15)
    const int ty  = tid >> 4;          // M direction (0..15)
    const int m0  = ty * 8;
    const int n0  = tx * 8;

    // 8x8 fp32 micro-tile held as 8x4 packed f32x2 accumulators
    unsigned long long acc[8][4];
#pragma unroll
    for (int i = 0; i < 8; i++)
#pragma unroll
        for (int j = 0; j < 4; j++)
            acc[i][j] = 0ull;  // bit pattern of {0.0f, 0.0f}

    for (int k0 = 0; k0 < C_DIM; k0 += BK) {
        // --- load A tile (128 rows x 16 k), transpose into As[k][m] ---
#pragma unroll
        for (int l = 0; l < 2; l++) {
            int id = tid + l * 256;      // 0..511 float4 slots
            int r  = id >> 2;            // row 0..127
            int c4 = id & 3;             // float4 index within k-slab
            float4 v = *reinterpret_cast<const float4*>(
                Q + (size_t)(bm + r) * C_DIM + k0 + c4 * 4);
            As[c4 * 4 + 0][r] = v.x;
            As[c4 * 4 + 1][r] = v.y;
            As[c4 * 4 + 2][r] = v.z;
            As[c4 * 4 + 3][r] = v.w;
        }
        // --- load B tile (guarded for tail), transpose into Bs[k][n] ---
#pragma unroll
        for (int l = 0; l < 2; l++) {
            int id = tid + l * 256;
            int r  = id >> 2;
            int c4 = id & 3;
            int n  = bn + r;
            float4 v = make_float4(0.f, 0.f, 0.f, 0.f);
            if (n < M)
                v = *reinterpret_cast<const float4*>(
                    Bank + (size_t)n * C_DIM + k0 + c4 * 4);
            Bs[c4 * 4 + 0][r] = v.x;
            Bs[c4 * 4 + 1][r] = v.y;
            Bs[c4 * 4 + 2][r] = v.z;
            Bs[c4 * 4 + 3][r] = v.w;
        }
        __syncthreads();

#pragma unroll
        for (int kk = 0; kk < BK; kk++) {
            float a[8];
            float4 av0 = *reinterpret_cast<const float4*>(&As[kk][m0]);
            float4 av1 = *reinterpret_cast<const float4*>(&As[kk][m0 + 4]);
            a[0] = av0.x; a[1] = av0.y; a[2] = av0.z; a[3] = av0.w;
            a[4] = av1.x; a[5] = av1.y; a[6] = av1.z; a[7] = av1.w;

            unsigned long long b2[4];
            const unsigned long long* bp =
                reinterpret_cast<const unsigned long long*>(&Bs[kk][n0]);
            b2[0] = bp[0]; b2[1] = bp[1]; b2[2] = bp[2]; b2[3] = bp[3];

#pragma unroll
            for (int i = 0; i < 8; i++) {
                unsigned long long a2;
                asm("mov.b64 %0, {%1, %2};" : "=l"(a2) : "f"(a[i]), "f"(a[i]));
#pragma unroll
                for (int j = 0; j < 4; j++)
                    asm("fma.rn.f32x2 %0, %1, %2, %0;"
                        : "+l"(acc[i][j]) : "l"(a2), "l"(b2[j]));
            }
        }
        __syncthreads();
    }

    // --- epilogue: score = bsq[n] - 2*dot ---
#pragma unroll
    for (int i = 0; i < 8; i++) {
        int gm = bm + m0 + i;  // query row (< B always)
        float* outrow = g_score + (size_t)gm * M;
#pragma unroll
        for (int j = 0; j < 4; j++) {
            float lo, hi;
            asm("mov.b64 {%0, %1}, %2;" : "=f"(lo), "=f"(hi) : "l"(acc[i][j]));
            int n = bn + n0 + 2 * j;
            if (n < M)     outrow[n]     = g_bsq[n]     - 2.0f * lo;
            if (n + 1 < M) outrow[n + 1] = g_bsq[n + 1] - 2.0f * hi;
        }
    }
}

// ---------------------------------------------------------------------------
// Kernel 3: per-query top-16 selection + trajectory gather.
// One CTA (256 threads) per query.
// ---------------------------------------------------------------------------
__device__ __forceinline__ bool better(float s1, int i1, float s2, int i2) {
    return (s1 < s2) || (s1 == s2 && i1 < i2);
}

__global__ __launch_bounds__(256)
void select_gather_kernel(const float* __restrict__ traj,
                          float* __restrict__ out,
                          int M, int TD) {
    const int q   = blockIdx.x;
    const int tid = threadIdx.x;
    const float* row = g_score + (size_t)q * M;

    // thread-local sorted (ascending) top-16
    float ls[KSEL];
    int   li[KSEL];
#pragma unroll
    for (int j = 0; j < KSEL; j++) { ls[j] = FLT_MAX; li[j] = INT_MAX; }
    float worst = FLT_MAX;

    for (int m = tid; m < M; m += 256) {
        float s = row[m];
        if (s < worst) {
            float cs = s; int ci = m;
#pragma unroll
            for (int j = 0; j < KSEL; j++) {
                if (cs < ls[j]) {
                    float ts = ls[j]; ls[j] = cs; cs = ts;
                    int   ti = li[j]; li[j] = ci; ci = ti;
                }
            }
            worst = ls[KSEL - 1];
        }
    }

    __shared__ float ss[256 * KSEL];
    __shared__ int   si[256 * KSEL];
    __shared__ float rs[256];
    __shared__ int   ri[256];
    __shared__ int   rslot[256];
    __shared__ int   winners[KSEL];

#pragma unroll
    for (int j = 0; j < KSEL; j++) {
        ss[tid * KSEL + j] = ls[j];
        si[tid * KSEL + j] = li[j];
    }
    __syncthreads();

    for (int r = 0; r < KSEL; r++) {
        float bs = FLT_MAX; int bi = INT_MAX; int bslot = tid * KSEL;
#pragma unroll
        for (int j = 0; j < KSEL; j++) {
            int idx = tid * KSEL + j;
            if (better(ss[idx], si[idx], bs, bi)) {
                bs = ss[idx]; bi = si[idx]; bslot = idx;
            }
        }
        rs[tid] = bs; ri[tid] = bi; rslot[tid] = bslot;
        __syncthreads();
        for (int off = 128; off > 0; off >>= 1) {
            if (tid < off) {
                if (better(rs[tid + off], ri[tid + off], rs[tid], ri[tid])) {
                    rs[tid] = rs[tid + off];
                    ri[tid] = ri[tid + off];
                    rslot[tid] = rslot[tid + off];
                }
            }
            __syncthreads();
        }
        if (tid == 0) {
            winners[r] = ri[0];
            ss[rslot[0]] = FLT_MAX;
            si[rslot[0]] = INT_MAX;
        }
        __syncthreads();
    }

    // gather trajectories: KSEL * TD floats per query
    for (int t = tid; t < KSEL * TD; t += 256) {
        int r = t / TD;
        int c = t - r * TD;
        out[(size_t)q * KSEL * TD + t] = traj[(size_t)winners[r] * TD + c];
    }
}

// ---------------------------------------------------------------------------
// Launch
// ---------------------------------------------------------------------------
extern "C" void kernel_launch(void* const* d_in, const int* in_sizes, int n_in,
                              void* d_out, int out_size) {
    const float* Q    = (const float*)d_in[0];
    const float* Bank = (const float*)d_in[1];
    const float* Traj = (const float*)d_in[2];
    float* out = (float*)d_out;

    const int C = C_DIM;
    const int B = in_sizes[0] / C;        // 256
    const int M = in_sizes[1] / C;        // 200000
    const int TD = in_sizes[2] / M;       // 24

    // 1) bank squared norms (one warp per row, 8 rows per CTA)
    {
        int warps = M;
        int ctas  = (warps * 32 + 255) / 256;
        bank_sq_kernel<<<ctas, 256>>>(Bank, M);
    }
    // 2) score GEMM
    {
        dim3 grid((M + BN - 1) / BN, (B + BM - 1) / BM);
        gemm_score_kernel<<<grid, 256>>>(Q, Bank, M);
    }
    // 3) selection + gather
    {
        select_gather_kernel<<<B, 256>>>(Traj, out, M, TD);
    }
}

// round 6
// speedup vs baseline: 3.0259x; 3.0259x over previous
#include <cuda_runtime.h>
#include <cuda_bf16.h>
#include <cfloat>
#include <climits>
#include <cstdint>

// ---------------------------------------------------------------------------
// Problem shape (fixed):
//   query [B=256,1024] f32, bank [M=200000,1024] f32, traj [M,8,3] f32, k=16
// Output: traj[nn_idx] sorted by ascending L2 dist, ties -> lower index.
// Strategy: bf16 mma.sync coarse scores -> top-64 candidates -> exact fp32
// rescore -> top-16 -> gather.  (tcgen05 unavailable: harness compiles via
// compute_103, which rejects tcgen05; mma.sync bf16 is arch-agnostic PTX.)
// ---------------------------------------------------------------------------

#define C_DIM   1024
#define B_MAX   256
#define M_MAX   200000
#define KSEL    16
#define NCAND   64

// __device__ scratch (allocation-free rule)
__device__ __align__(16) float          g_score[(size_t)B_MAX * M_MAX];
__device__ __align__(16) float          g_bsq[M_MAX];
__device__ __align__(16) __nv_bfloat16  g_bank_bf[(size_t)M_MAX * C_DIM];
__device__ __align__(16) __nv_bfloat16  g_q_bf[(size_t)B_MAX * C_DIM];
__device__                int           g_cand[B_MAX * NCAND];

#define SMEM_SWIZZLE_128B(o) ((o) ^ (((o) >> 3) & 0x70))

__device__ __forceinline__ uint32_t smem_to_u32(const void* p) {
    uint32_t a;
    asm("{ .reg .u64 t; cvta.to.shared.u64 t, %1; cvt.u32.u64 %0, t; }"
        : "=r"(a) : "l"(p));
    return a;
}
__device__ __forceinline__ void cp_async16(uint32_t dst, const void* src, int srcsize) {
    asm volatile("cp.async.cg.shared.global [%0], [%1], 16, %2;"
                 :: "r"(dst), "l"(src), "r"(srcsize));
}
__device__ __forceinline__ void cp_commit() {
    asm volatile("cp.async.commit_group;");
}
template <int N>
__device__ __forceinline__ void cp_wait() {
    asm volatile("cp.async.wait_group %0;" :: "n"(N));
}
__device__ __forceinline__ void ldmx4(uint32_t& r0, uint32_t& r1,
                                      uint32_t& r2, uint32_t& r3, uint32_t addr) {
    asm volatile("ldmatrix.sync.aligned.m8n8.x4.shared.b16 {%0,%1,%2,%3}, [%4];"
                 : "=r"(r0), "=r"(r1), "=r"(r2), "=r"(r3) : "r"(addr));
}
__device__ __forceinline__ void mma16816(float* c, const uint32_t* a, const uint32_t* b) {
    asm volatile(
        "mma.sync.aligned.m16n8k16.row.col.f32.bf16.bf16.f32 "
        "{%0,%1,%2,%3}, {%4,%5,%6,%7}, {%8,%9}, {%0,%1,%2,%3};"
        : "+f"(c[0]), "+f"(c[1]), "+f"(c[2]), "+f"(c[3])
        : "r"(a[0]), "r"(a[1]), "r"(a[2]), "r"(a[3]), "r"(b[0]), "r"(b[1]));
}

// ---------------------------------------------------------------------------
// Kernel 1: fp32 -> bf16 convert, fused squared norms. One warp per row.
// ---------------------------------------------------------------------------
__global__ void convert_kernel(const float* __restrict__ src,
                               __nv_bfloat16* __restrict__ dst,
                               float* __restrict__ bsq, int rows) {
    int warp = (blockIdx.x * blockDim.x + threadIdx.x) >> 5;
    int lane = threadIdx.x & 31;
    if (warp >= rows) return;
    const float4* srow = reinterpret_cast<const float4*>(src + (size_t)warp * C_DIM);
    __nv_bfloat162* drow = reinterpret_cast<__nv_bfloat162*>(dst + (size_t)warp * C_DIM);
    float acc = 0.f;
#pragma unroll
    for (int i = 0; i < C_DIM / 128; i++) {
        int j = i * 32 + lane;
        float4 v = srow[j];
        acc += v.x * v.x + v.y * v.y + v.z * v.z + v.w * v.w;
        drow[2 * j]     = __nv_bfloat162(__float2bfloat16(v.x), __float2bfloat16(v.y));
        drow[2 * j + 1] = __nv_bfloat162(__float2bfloat16(v.z), __float2bfloat16(v.w));
    }
    if (bsq) {
#pragma unroll
        for (int off = 16; off > 0; off >>= 1)
            acc += __shfl_xor_sync(0xffffffffu, acc, off);
        if (lane == 0) bsq[warp] = acc;
    }
}

// ---------------------------------------------------------------------------
// Kernel 2: coarse bf16 GEMM via mma.sync.m16n8k16.
//   CTA tile 128(q) x 128(n), K chunks of 64, cp.async double buffer.
//   8 warps: warp_m in {0,1} (64 rows), warp_n in {0..3} (32 cols).
//   score[q][n] = bsq[n] - 2*dot written directly from fragments.
// ---------------------------------------------------------------------------
#define BM   128
#define BN   128
#define BKC  64                      // bf16 per K chunk -> 128B rows, SW128
#define NCH  (C_DIM / BKC)           // 16
#define TILE_BYTES (BM * 128)        // 16 KB per operand tile
#define GEMM_SMEM  (4 * TILE_BYTES)  // A0,B0,A1,B1 = 64 KB

__global__ __launch_bounds__(256, 2)
void mma_gemm_kernel(int M) {
    extern __shared__ char smem[];
    const uint32_t sb = smem_to_u32(smem);
    const int tid  = threadIdx.x;
    const int wid  = tid >> 5;
    const int lane = tid & 31;
    const int qt = blockIdx.x;            // 0..1 query tile (fast dim -> L2 reuse)
    const int bn = blockIdx.y * BN;       // bank tile base
    const int warp_m = wid & 1;
    const int warp_n = wid >> 1;

    const __nv_bfloat16* Abase = g_q_bf + (size_t)qt * BM * C_DIM;

    // per-thread cp.async slots: 4 x 16B for A, 4 x 16B for B per buffer
    int lrow[4], lu[4];
#pragma unroll
    for (int l = 0; l < 4; l++) {
        int id = tid + l * 256;           // 0..1023
        lrow[l] = id >> 3;                // 0..127
        lu[l]   = id & 7;                 // 16B unit within 128B row
    }

    auto issue_loads = [&](int c, int buf) {
        int k0 = c * BKC;
        uint32_t As = sb + buf * 2 * TILE_BYTES;
        uint32_t Bs = As + TILE_BYTES;
#pragma unroll
        for (int l = 0; l < 4; l++) {
            uint32_t so = SMEM_SWIZZLE_128B((uint32_t)(lrow[l] * 128 + lu[l] * 16));
            cp_async16(As + so, Abase + (size_t)lrow[l] * C_DIM + k0 + lu[l] * 8, 16);
            int n = bn + lrow[l];
            const void* srcB = g_bank_bf + (size_t)(n < M ? n : 0) * C_DIM + k0 + lu[l] * 8;
            cp_async16(Bs + so, srcB, n < M ? 16 : 0);
        }
        cp_commit();
    };

    float acc[4][4][4];
#pragma unroll
    for (int mi = 0; mi < 4; mi++)
#pragma unroll
        for (int nj = 0; nj < 4; nj++)
#pragma unroll
            for (int e = 0; e < 4; e++) acc[mi][nj][e] = 0.f;

    issue_loads(0, 0);

    for (int c = 0; c < NCH; c++) {
        int buf = c & 1;
        if (c + 1 < NCH) {
            issue_loads(c + 1, buf ^ 1);
            cp_wait<1>();
        } else {
            cp_wait<0>();
        }
        __syncthreads();

        uint32_t As = sb + buf * 2 * TILE_BYTES;
        uint32_t Bs = As + TILE_BYTES;
#pragma unroll
        for (int ks = 0; ks < BKC / 16; ks++) {
            uint32_t a[4][4];
            int arow = warp_m * 64 + (lane & 15);
            int akb  = ks * 16 + (lane >> 4) * 8;
#pragma unroll
            for (int mi = 0; mi < 4; mi++) {
                uint32_t so = SMEM_SWIZZLE_128B(
                    (uint32_t)((arow + mi * 16) * 128 + akb * 2));
                ldmx4(a[mi][0], a[mi][1], a[mi][2], a[mi][3], As + so);
            }
            uint32_t b[4][2];
            int g = lane >> 3;            // 0..3 address group
#pragma unroll
            for (int pair = 0; pair < 2; pair++) {
                int brow = warp_n * 32 + pair * 16 + ((g >> 1) & 1) * 8 + (lane & 7);
                int bkb  = ks * 16 + (g & 1) * 8;
                uint32_t so = SMEM_SWIZZLE_128B((uint32_t)(brow * 128 + bkb * 2));
                uint32_t r0, r1, r2, r3;
                ldmx4(r0, r1, r2, r3, Bs + so);
                b[2 * pair][0] = r0; b[2 * pair][1] = r1;
                b[2 * pair + 1][0] = r2; b[2 * pair + 1][1] = r3;
            }
#pragma unroll
            for (int mi = 0; mi < 4; mi++)
#pragma unroll
                for (int nj = 0; nj < 4; nj++)
                    mma16816(acc[mi][nj], a[mi], b[nj]);
        }
        __syncthreads();
    }

    // --- epilogue: score = bsq[n] - 2*dot, straight from fragments ---
    const int qbase = qt * BM + warp_m * 64;
    const int nbase = bn + warp_n * 32;
#pragma unroll
    for (int mi = 0; mi < 4; mi++) {
#pragma unroll
        for (int nj = 0; nj < 4; nj++) {
            int n0 = nbase + nj * 8 + (lane & 3) * 2;
            if (n0 + 1 < M) {
                float b0 = g_bsq[n0], b1 = g_bsq[n0 + 1];
                int q0 = qbase + mi * 16 + (lane >> 2);
                float2 v0 = make_float2(b0 - 2.f * acc[mi][nj][0],
                                        b1 - 2.f * acc[mi][nj][1]);
                float2 v1 = make_float2(b0 - 2.f * acc[mi][nj][2],
                                        b1 - 2.f * acc[mi][nj][3]);
                *reinterpret_cast<float2*>(g_score + (size_t)q0 * M + n0) = v0;
                *reinterpret_cast<float2*>(g_score + (size_t)(q0 + 8) * M + n0) = v1;
            } else if (n0 < M) {
                float b0 = g_bsq[n0];
                int q0 = qbase + mi * 16 + (lane >> 2);
                g_score[(size_t)q0 * M + n0]       = b0 - 2.f * acc[mi][nj][0];
                g_score[(size_t)(q0 + 8) * M + n0] = b0 - 2.f * acc[mi][nj][2];
            }
        }
    }
}

// ---------------------------------------------------------------------------
// Kernel 3: per-query coarse top-64 candidates.
// Thread-local top-8, merge 2048 in SMEM, bitonic sort, take first 64.
// ---------------------------------------------------------------------------
__device__ __forceinline__ unsigned long long pack_key(float s, int idx) {
    unsigned u = __float_as_uint(s);
    u = (u & 0x80000000u) ? ~u : (u | 0x80000000u);
    return ((unsigned long long)u << 32) | (unsigned)idx;
}

__global__ __launch_bounds__(256)
void select_cand_kernel(int M) {
    const int q   = blockIdx.x;
    const int tid = threadIdx.x;
    const float* row = g_score + (size_t)q * M;

    float ls[8]; int li[8];
#pragma unroll
    for (int j = 0; j < 8; j++) { ls[j] = FLT_MAX; li[j] = INT_MAX; }
    float worst = FLT_MAX;
    for (int m = tid; m < M; m += 256) {
        float s = row[m];
        if (s < worst) {
            float cs = s; int ci = m;
#pragma unroll
            for (int j = 0; j < 8; j++) {
                if (cs < ls[j] || (cs == ls[j] && ci < li[j])) {
                    float ts = ls[j]; ls[j] = cs; cs = ts;
                    int   ti = li[j]; li[j] = ci; ci = ti;
                }
            }
            worst = ls[7];
        }
    }

    __shared__ unsigned long long keys[2048];
#pragma unroll
    for (int j = 0; j < 8; j++)
        keys[tid * 8 + j] = pack_key(ls[j], li[j]);
    __syncthreads();

    for (int k = 2; k <= 2048; k <<= 1) {
        for (int j = k >> 1; j > 0; j >>= 1) {
            for (int t = tid; t < 2048; t += 256) {
                int ixj = t ^ j;
                if (ixj > t) {
                    unsigned long long a = keys[t], b = keys[ixj];
                    bool up = ((t & k) == 0);
                    if ((a > b) == up) { keys[t] = b; keys[ixj] = a; }
                }
            }
            __syncthreads();
        }
    }
    if (tid < NCAND)
        g_cand[q * NCAND + tid] = (int)(keys[tid] & 0xffffffffu);
}

// ---------------------------------------------------------------------------
// Kernel 4: exact fp32 rescore of 64 candidates, top-16, gather trajectories.
// ---------------------------------------------------------------------------
__global__ __launch_bounds__(256)
void rescore_gather_kernel(const float* __restrict__ Q,
                           const float* __restrict__ Bank,
                           const float* __restrict__ traj,
                           float* __restrict__ out, int TD) {
    const int q   = blockIdx.x;
    const int tid = threadIdx.x;
    const int wid = tid >> 5, lane = tid & 31;

    __shared__ __align__(16) float qrow[C_DIM];
    __shared__ float cs[NCAND];
    __shared__ int   ci[NCAND];
    __shared__ unsigned long long k64[NCAND];

    for (int t = tid; t < C_DIM; t += 256)
        qrow[t] = Q[(size_t)q * C_DIM + t];
    __syncthreads();

    const float4* q4 = reinterpret_cast<const float4*>(qrow);
    for (int cand = wid; cand < NCAND; cand += 8) {
        int idx = g_cand[q * NCAND + cand];
        const float4* b4 = reinterpret_cast<const float4*>(Bank + (size_t)idx * C_DIM);
        float acc = 0.f;
#pragma unroll
        for (int j = lane; j < C_DIM / 4; j += 32) {
            float4 a = q4[j], b = b4[j];
            acc += a.x * b.x + a.y * b.y + a.z * b.z + a.w * b.w;
        }
#pragma unroll
        for (int off = 16; off > 0; off >>= 1)
            acc += __shfl_xor_sync(0xffffffffu, acc, off);
        if (lane == 0) { cs[cand] = g_bsq[idx] - 2.0f * acc; ci[cand] = idx; }
    }
    __syncthreads();

    if (tid < NCAND) k64[tid] = pack_key(cs[tid], ci[tid]);
    __syncthreads();
    for (int k = 2; k <= NCAND; k <<= 1) {
        for (int j = k >> 1; j > 0; j >>= 1) {
            for (int t = tid; t < NCAND; t += 256) {
                int ixj = t ^ j;
                if (ixj > t) {
                    unsigned long long a = k64[t], b = k64[ixj];
                    bool up = ((t & k) == 0);
                    if ((a > b) == up) { k64[t] = b; k64[ixj] = a; }
                }
            }
            __syncthreads();
        }
    }

    for (int t = tid; t < KSEL * TD; t += 256) {
        int r = t / TD;
        int c = t - r * TD;
        int idx = (int)(k64[r] & 0xffffffffu);
        out[(size_t)q * KSEL * TD + t] = traj[(size_t)idx * TD + c];
    }
}

// ---------------------------------------------------------------------------
// Launch
// ---------------------------------------------------------------------------
extern "C" void kernel_launch(void* const* d_in, const int* in_sizes, int n_in,
                              void* d_out, int out_size) {
    const float* Q    = (const float*)d_in[0];
    const float* Bank = (const float*)d_in[1];
    const float* Traj = (const float*)d_in[2];
    float* out = (float*)d_out;

    const int C  = C_DIM;
    const int B  = in_sizes[0] / C;    // 256
    const int M  = in_sizes[1] / C;    // 200000
    const int TD = in_sizes[2] / M;    // 24

    cudaFuncSetAttribute(mma_gemm_kernel,
                         cudaFuncAttributeMaxDynamicSharedMemorySize, GEMM_SMEM);

    float* bsq_p = nullptr;
    __nv_bfloat16 *bankbf_p = nullptr, *qbf_p = nullptr;
    cudaGetSymbolAddress((void**)&bsq_p, g_bsq);
    cudaGetSymbolAddress((void**)&bankbf_p, g_bank_bf);
    cudaGetSymbolAddress((void**)&qbf_p, g_q_bf);

    // 1) convert bank (+bsq) and query to bf16
    {
        int ctas = (M * 32 + 255) / 256;
        convert_kernel<<<ctas, 256>>>(Bank, bankbf_p, bsq_p, M);
        int qctas = (B * 32 + 255) / 256;
        convert_kernel<<<qctas, 256>>>(Q, qbf_p, nullptr, B);
    }
    // 2) coarse bf16 mma GEMM (q tile in fast grid dim for bank L2 reuse)
    {
        dim3 grid(B / BM, (M + BN - 1) / BN);
        mma_gemm_kernel<<<grid, 256, GEMM_SMEM>>>(M);
    }
    // 3) coarse top-64 candidates per query
    select_cand_kernel<<<B, 256>>>(M);
    // 4) exact fp32 rescore + top-16 + gather
    rescore_gather_kernel<<<B, 256>>>(Q, Bank, Traj, out, TD);
}